// round 12
// baseline (speedup 1.0000x reference)
#include <cuda_runtime.h>
#include <cuda_fp16.h>
#include <math.h>
#include <cstdint>

// ---------------------------------------------------------------------------
// Problem constants
// ---------------------------------------------------------------------------
constexpr int B  = 2;
constexpr int T  = 8192;
constexpr int C  = 1024;
constexpr int H  = 16;
constexpr int BS = 64;
constexpr int LW = 128;
constexpr int D  = 64;
constexpr int WN = BS + LW;     // 192
constexpr int NB = T / BS;      // 128
constexpr int M  = B * T;       // 16384

// ---------------------------------------------------------------------------
// GEMM config: mma.sync m16n8k16 fp16, CTA tile 128x128x64, 8 warps (32x64),
// 3-stage cp.async pipeline, 2 CTAs/SM. Per-warp ks rotation staggers LDSM
// bursts against MMA tails across resident warps.
// ---------------------------------------------------------------------------
constexpr int GBM = 128;
constexpr int GBN = 128;
constexpr int GBK = 64;                       // 64 fp16 = 128B rows
constexpr int NKT = C / GBK;                  // 16
constexpr int AST = GBM * GBK * 2;            // 16384 B
constexpr int BST = GBN * GBK * 2;            // 16384 B
constexpr int SM_B_OFF = 3 * AST;             // 49152
constexpr int SM_BIAS  = 3 * AST + 3 * BST;   // 98304
constexpr int SM_GEMM  = SM_BIAS + GBN * 4;   // 98816

// ---------------------------------------------------------------------------
// Attention smem layout (bytes), fp16 tiles, 128B rows.
// P panels (24KB) OVERLAY the dead Q+K region (32KB) after QK completes.
// ---------------------------------------------------------------------------
constexpr int SMQ   = 0;        // 64 x 128B  = 8KB
constexpr int SMK   = 8192;     // 192 x 128B = 24KB
constexpr int SMV   = 32768;    // 192 x 128B = 24KB
constexpr int SMP   = 0;        // 3 panels x 64 x 128B = 24KB (overlays Q+K)
constexpr int SMRA  = 57344;    // 64 x 4 f32 (max reduce)
constexpr int SMRB  = 58368;    // 64 x 4 f32 (sum reduce)
constexpr int SMEM_ATTN = 59392;
constexpr int ATHR = 512;

// ---------------------------------------------------------------------------
// Scratch
// ---------------------------------------------------------------------------
__device__ __align__(16) __half g_x16[3][(size_t)M * C];   // fp16 inputs
__device__ __align__(16) __half g_w16[4][(size_t)C * C];   // fp16 weights
__device__ __align__(16) __half g_q[(size_t)M * C];
__device__ __align__(16) __half g_k[(size_t)M * C];
__device__ __align__(16) __half g_v[(size_t)M * C];
__device__ __align__(16) __half g_a[(size_t)M * C];

struct GemmArgs {
    const __half* A[3];
    const __half* W[3];
    const float*  bias[3];
    void*         Y[3];
    float         alpha[3];
};

// ---------------------------------------------------------------------------
// PTX helpers (base sm_103-safe)
// ---------------------------------------------------------------------------
__device__ __forceinline__ uint32_t smem_u32(const void* p) {
    uint32_t a;
    asm("{ .reg .u64 t; cvta.to.shared.u64 t, %1; cvt.u32.u64 %0, t; }" : "=r"(a) : "l"(p));
    return a;
}

#define CP_ASYNC16(dst, src) \
    asm volatile("cp.async.cg.shared.global [%0], [%1], 16;" :: "r"(dst), "l"(src) : "memory")
#define CP_COMMIT() asm volatile("cp.async.commit_group;" ::: "memory")
#define CP_WAIT(n)  asm volatile("cp.async.wait_group %0;" :: "n"(n) : "memory")

#define LDSM_X4(r, addr) \
    asm volatile("ldmatrix.sync.aligned.m8n8.x4.shared.b16 {%0,%1,%2,%3}, [%4];" \
        : "=r"((r)[0]), "=r"((r)[1]), "=r"((r)[2]), "=r"((r)[3]) : "r"(addr))

#define LDSM_X4_T(r, addr) \
    asm volatile("ldmatrix.sync.aligned.m8n8.x4.trans.shared.b16 {%0,%1,%2,%3}, [%4];" \
        : "=r"((r)[0]), "=r"((r)[1]), "=r"((r)[2]), "=r"((r)[3]) : "r"(addr))

#define MMA_F16(d, a, b0, b1) \
    asm volatile("mma.sync.aligned.m16n8k16.row.col.f32.f16.f16.f32 " \
        "{%0,%1,%2,%3}, {%4,%5,%6,%7}, {%8,%9}, {%0,%1,%2,%3};" \
        : "+f"((d)[0]), "+f"((d)[1]), "+f"((d)[2]), "+f"((d)[3]) \
        : "r"((a)[0]), "r"((a)[1]), "r"((a)[2]), "r"((a)[3]), "r"(b0), "r"(b1))

// ---------------------------------------------------------------------------
// Prepass: all fp32 -> fp16 conversions in ONE launch.
// ---------------------------------------------------------------------------
constexpr size_t PER4A = (size_t)M * C / 4;   // 4194304 float4 per activation
constexpr size_t PER4W = (size_t)C * C / 4;   // 262144 float4 per weight
constexpr size_t CONV_TOTAL = 3 * PER4A + 4 * PER4W;

__global__ __launch_bounds__(256)
void conv_all(const float4* __restrict__ q, const float4* __restrict__ k,
              const float4* __restrict__ v,
              const float4* __restrict__ w0, const float4* __restrict__ w1,
              const float4* __restrict__ w2, const float4* __restrict__ w3)
{
    size_t i = (size_t)blockIdx.x * 256 + threadIdx.x;
    const float4* src;
    __half2* dst;
    if (i < 3 * PER4A) {
        const int which = (int)(i / PER4A);
        const size_t off = i - (size_t)which * PER4A;
        src = (which == 0 ? q : which == 1 ? k : v) + off;
        dst = (__half2*)&g_x16[which][off * 4];
    } else {
        i -= 3 * PER4A;
        const int which = (int)(i / PER4W);
        const size_t off = i - (size_t)which * PER4W;
        src = (which == 0 ? w0 : which == 1 ? w1 : which == 2 ? w2 : w3) + off;
        dst = (__half2*)&g_w16[which][off * 4];
    }
    float4 x = *src;
    dst[0] = __floats2half2_rn(x.x, x.y);
    dst[1] = __floats2half2_rn(x.z, x.w);
}

// ---------------------------------------------------------------------------
// fp16 GEMM: Y[m,n] = alpha * (sum_k A[m,k] * W[n,k] + bias[n])
// ---------------------------------------------------------------------------
template <bool HALF_OUT>
__global__ __launch_bounds__(256, 2)
void gemm_mma(const GemmArgs args)
{
    extern __shared__ char smem[];
    const uint32_t sA = smem_u32(smem);
    const uint32_t sB = sA + SM_B_OFF;
    float* bsm = (float*)(smem + SM_BIAS);

    const int z = blockIdx.z;
    const __half* A    = args.A[z];
    const __half* Wt   = args.W[z];
    const float*  bias = args.bias[z];
    void*         Y    = args.Y[z];
    const float alpha  = args.alpha[z];

    const int tid  = threadIdx.x;
    const int wid  = tid >> 5;
    const int lane = tid & 31;
    const int bm   = blockIdx.y * GBM;
    const int n0   = blockIdx.x * GBN;

    if (tid < GBN / 4)
        *(float4*)(bsm + tid * 4) = *(const float4*)(bias + n0 + tid * 4);

    auto loadA = [&](int slot, int kt) {
        const __half* src = A + (size_t)bm * C + kt * GBK;
        const uint32_t base = sA + slot * AST;
        #pragma unroll
        for (int c = 0; c < 4; c++) {
            const int ci = tid + c * 256;
            const int r = ci >> 3, g = ci & 7;
            CP_ASYNC16(base + r * 128 + ((g * 16) ^ ((r & 7) * 16)),
                       src + (size_t)r * C + g * 8);
        }
    };
    auto loadB = [&](int slot, int kt) {
        const __half* src = Wt + (size_t)n0 * C + kt * GBK;
        const uint32_t base = sB + slot * BST;
        #pragma unroll
        for (int c = 0; c < 4; c++) {
            const int ci = tid + c * 256;
            const int r = ci >> 3, g = ci & 7;
            CP_ASYNC16(base + r * 128 + ((g * 16) ^ ((r & 7) * 16)),
                       src + (size_t)r * C + g * 8);
        }
    };

    loadA(0, 0); loadB(0, 0); CP_COMMIT();
    loadA(1, 1); loadB(1, 1); CP_COMMIT();

    float acc[2][8][4];
    #pragma unroll
    for (int i = 0; i < 2; i++)
        #pragma unroll
        for (int j = 0; j < 8; j++)
            #pragma unroll
            for (int l = 0; l < 4; l++) acc[i][j][l] = 0.f;

    const int r8 = lane & 7;
    const int qa = lane >> 3;
    const int wm = (wid & 3) * 32;
    const int wn = (wid >> 2) * 64;
    const uint32_t a_rb   = (wm + (qa & 1) * 8 + r8) * 128;
    const uint32_t a_ksel = (uint32_t)(qa >> 1) * 16;
    const uint32_t b_rb   = (wn + (qa >> 1) * 8 + r8) * 128;
    const uint32_t b_ksel = (uint32_t)(qa & 1) * 16;
    const uint32_t xorp   = (uint32_t)r8 * 16;
    const int ksrot = wid & 3;     // per-warp ks phase rotation

    #pragma unroll 3
    for (int kt = 0; kt < NKT; kt++) {
        if (kt < NKT - 2) { CP_WAIT(1); } else { CP_WAIT(0); }
        __syncthreads();
        if (kt + 2 < NKT) {
            const int s2 = (kt + 2) % 3;
            loadA(s2, kt + 2); loadB(s2, kt + 2); CP_COMMIT();
        }
        const int slot = kt % 3;
        const uint32_t aBase = sA + slot * AST + a_rb;
        const uint32_t bBase = sB + slot * BST + b_rb;

        #pragma unroll
        for (int kss = 0; kss < 4; kss++) {
            const int ks = (kss + ksrot) & 3;   // staggered start per warp
            const uint32_t akoff = ((uint32_t)ks * 32 + a_ksel) ^ xorp;
            const uint32_t bkoff = ((uint32_t)ks * 32 + b_ksel) ^ xorp;
            uint32_t af[2][4], bf[4][4];
            #pragma unroll
            for (int mt = 0; mt < 2; mt++)
                LDSM_X4(af[mt], aBase + mt * (16 * 128) + akoff);
            #pragma unroll
            for (int p = 0; p < 4; p++)
                LDSM_X4(bf[p], bBase + p * (16 * 128) + bkoff);
            #pragma unroll
            for (int mt = 0; mt < 2; mt++)
                #pragma unroll
                for (int p = 0; p < 4; p++) {
                    MMA_F16(acc[mt][2 * p + 0], af[mt], bf[p][0], bf[p][1]);
                    MMA_F16(acc[mt][2 * p + 1], af[mt], bf[p][2], bf[p][3]);
                }
        }
    }

    const int erow  = bm + wm + (lane >> 2);
    const int ecol0 = wn + 2 * (lane & 3);
    #pragma unroll
    for (int mt = 0; mt < 2; mt++) {
        #pragma unroll
        for (int nt = 0; nt < 8; nt++) {
            const int col = ecol0 + nt * 8;
            const float b0 = bsm[col], b1 = bsm[col + 1];
            const float x0 = alpha * (acc[mt][nt][0] + b0);
            const float x1 = alpha * (acc[mt][nt][1] + b1);
            const float x2 = alpha * (acc[mt][nt][2] + b0);
            const float x3 = alpha * (acc[mt][nt][3] + b1);
            if (HALF_OUT) {
                __half* Yh = (__half*)Y;
                *(__half2*)(Yh + (size_t)(erow + mt * 16)     * C + n0 + col) = __floats2half2_rn(x0, x1);
                *(__half2*)(Yh + (size_t)(erow + mt * 16 + 8) * C + n0 + col) = __floats2half2_rn(x2, x3);
            } else {
                float* Yf = (float*)Y;
                float2 lo; lo.x = x0; lo.y = x1;
                float2 hi; hi.x = x2; hi.y = x3;
                *(float2*)(Yf + (size_t)(erow + mt * 16)     * C + n0 + col) = lo;
                *(float2*)(Yf + (size_t)(erow + mt * 16 + 8) * C + n0 + col) = hi;
            }
        }
    }
}

// ---------------------------------------------------------------------------
// fp16 tensor-core block-local attention, 512 threads, 2 CTAs/SM.
// (Unchanged from R8 — known-good.)
// ---------------------------------------------------------------------------
__global__ __launch_bounds__(ATHR, 2)
void attn_kernel(const __half* __restrict__ q, const __half* __restrict__ k,
                 const __half* __restrict__ v, __half* __restrict__ o)
{
    extern __shared__ char smem[];
    const uint32_t sb = smem_u32(smem);
    float* redA = (float*)(smem + SMRA);
    float* redB = (float*)(smem + SMRB);

    const int nb  = blockIdx.x;
    const int h   = blockIdx.y;
    const int b   = blockIdx.z;
    const int tid = threadIdx.x;
    const int wid  = tid >> 5;
    const int lane = tid & 31;
    const int start = nb * BS;
    const size_t rowBase = (size_t)b * T * C + (size_t)h * D;

    const __half* qp = q + rowBase;
    const __half* kp = k + rowBase;
    const __half* vp = v + rowBase;

    {
        {   // Q: 64 rows x 8 granules = 512
            const int r = tid >> 3, g = tid & 7;
            CP_ASYNC16(sb + SMQ + r * 128 + ((g * 16) ^ ((r & 7) * 16)),
                       qp + (size_t)(start + r) * C + g * 8);
        }
        #pragma unroll
        for (int i = 0; i < 3; i++) {   // K: 192 x 8 = 1536
            const int idx = tid + i * ATHR;
            const int r = idx >> 3, g = idx & 7;
            int p = start - LW / 2 + r;
            p = p < 0 ? 0 : (p >= T ? T - 1 : p);
            CP_ASYNC16(sb + SMK + r * 128 + ((g * 16) ^ ((r & 7) * 16)),
                       kp + (size_t)p * C + g * 8);
        }
        CP_COMMIT();
        #pragma unroll
        for (int i = 0; i < 3; i++) {   // V: 192 x 8
            const int idx = tid + i * ATHR;
            const int r = idx >> 3, g = idx & 7;
            int p = start - LW / 2 + r;
            p = p < 0 ? 0 : (p >= T ? T - 1 : p);
            CP_ASYNC16(sb + SMV + r * 128 + ((g * 16) ^ ((r & 7) * 16)),
                       vp + (size_t)p * C + g * 8);
        }
        CP_COMMIT();
    }

    const int r8 = lane & 7;
    const int qa = lane >> 3;
    const uint32_t xorp = (uint32_t)r8 * 16;
    const int kg = wid >> 2;                  // k-group (QK) / d-group (PV)

    const int wmq = (wid & 3) * 16;
    const int wnq = kg * 48;
    const uint32_t aQ_rb = (wmq + (qa & 1) * 8 + r8) * 128;
    const uint32_t aQ_ks = (uint32_t)(qa >> 1) * 16;
    const uint32_t bK_rb = (wnq + (qa >> 1) * 8 + r8) * 128;
    const uint32_t bK_ks = (uint32_t)(qa & 1) * 16;

    float accS[6][4];
    #pragma unroll
    for (int i = 0; i < 6; i++)
        #pragma unroll
        for (int l = 0; l < 4; l++) accS[i][l] = 0.f;

    CP_WAIT(1);
    __syncthreads();

    #pragma unroll
    for (int ks = 0; ks < 4; ks++) {
        uint32_t af[4], bf[3][4];
        LDSM_X4(af, sb + SMQ + aQ_rb + (((uint32_t)ks * 32 + aQ_ks) ^ xorp));
        #pragma unroll
        for (int p = 0; p < 3; p++)
            LDSM_X4(bf[p], sb + SMK + bK_rb + p * (16 * 128) + (((uint32_t)ks * 32 + bK_ks) ^ xorp));
        #pragma unroll
        for (int p = 0; p < 3; p++) {
            MMA_F16(accS[2 * p + 0], af, bf[p][0], bf[p][1]);
            MMA_F16(accS[2 * p + 1], af, bf[p][2], bf[p][3]);
        }
    }

    const int r0 = wmq + (lane >> 2);
    const int r1 = r0 + 8;
    const int c0 = wnq + 2 * (lane & 3);

    float mx0 = -INFINITY, mx1 = -INFINITY;
    #pragma unroll
    for (int nt = 0; nt < 6; nt++) {
        const int ca = c0 + nt * 8, cb = ca + 1;
        const int pa = start - LW / 2 + ca, pb = pa + 1;
        const bool va = (pa >= 0) & (pa < T);
        const bool vb = (pb >= 0) & (pb < T);
        if (!va) { accS[nt][0] = -INFINITY; accS[nt][2] = -INFINITY; }
        if (!vb) { accS[nt][1] = -INFINITY; accS[nt][3] = -INFINITY; }
        mx0 = fmaxf(mx0, fmaxf(accS[nt][0], accS[nt][1]));
        mx1 = fmaxf(mx1, fmaxf(accS[nt][2], accS[nt][3]));
    }
    #pragma unroll
    for (int off = 1; off <= 2; off <<= 1) {
        mx0 = fmaxf(mx0, __shfl_xor_sync(0xffffffffu, mx0, off));
        mx1 = fmaxf(mx1, __shfl_xor_sync(0xffffffffu, mx1, off));
    }
    if ((lane & 3) == 0) { redA[r0 * 4 + kg] = mx0; redA[r1 * 4 + kg] = mx1; }
    __syncthreads();
    mx0 = fmaxf(fmaxf(redA[r0 * 4 + 0], redA[r0 * 4 + 1]),
                fmaxf(redA[r0 * 4 + 2], redA[r0 * 4 + 3]));
    mx1 = fmaxf(fmaxf(redA[r1 * 4 + 0], redA[r1 * 4 + 1]),
                fmaxf(redA[r1 * 4 + 2], redA[r1 * 4 + 3]));

    float s0 = 0.f, s1 = 0.f;
    #pragma unroll
    for (int nt = 0; nt < 6; nt++) {
        accS[nt][0] = __expf(accS[nt][0] - mx0);
        accS[nt][1] = __expf(accS[nt][1] - mx0);
        accS[nt][2] = __expf(accS[nt][2] - mx1);
        accS[nt][3] = __expf(accS[nt][3] - mx1);
        s0 += accS[nt][0] + accS[nt][1];
        s1 += accS[nt][2] + accS[nt][3];
    }
    #pragma unroll
    for (int off = 1; off <= 2; off <<= 1) {
        s0 += __shfl_xor_sync(0xffffffffu, s0, off);
        s1 += __shfl_xor_sync(0xffffffffu, s1, off);
    }
    if ((lane & 3) == 0) { redB[r0 * 4 + kg] = s0; redB[r1 * 4 + kg] = s1; }
    CP_WAIT(0);
    __syncthreads();
    const float inv0 = 1.f / (redB[r0 * 4 + 0] + redB[r0 * 4 + 1] +
                              redB[r0 * 4 + 2] + redB[r0 * 4 + 3]);
    const float inv1 = 1.f / (redB[r1 * 4 + 0] + redB[r1 * 4 + 1] +
                              redB[r1 * 4 + 2] + redB[r1 * 4 + 3]);

    #pragma unroll
    for (int nt = 0; nt < 6; nt++) {
        const int c = c0 + nt * 8;
        const int pan = c >> 6, cc = (c & 63) * 2;
        const uint32_t o0 = SMP + pan * 8192 + r0 * 128 + (cc ^ ((r0 & 7) * 16));
        const uint32_t o1 = SMP + pan * 8192 + r1 * 128 + (cc ^ ((r1 & 7) * 16));
        *(__half2*)(smem + o0) = __floats2half2_rn(accS[nt][0] * inv0, accS[nt][1] * inv0);
        *(__half2*)(smem + o1) = __floats2half2_rn(accS[nt][2] * inv1, accS[nt][3] * inv1);
    }
    __syncthreads();

    const int wmp = (wid & 3) * 16;
    const int wnp = kg * 16;
    const uint32_t aP_rb = (wmp + (qa & 1) * 8 + r8) * 128;
    const uint32_t aP_ks = (uint32_t)(qa >> 1) * 16;
    const uint32_t v_row = (qa & 1) * 8 + r8;
    const uint32_t v_doff = ((uint32_t)wnp * 2 + (uint32_t)(qa >> 1) * 16) ^ xorp;

    float accO[2][4];
    #pragma unroll
    for (int i = 0; i < 2; i++)
        #pragma unroll
        for (int l = 0; l < 4; l++) accO[i][l] = 0.f;

    #pragma unroll
    for (int pan = 0; pan < 3; pan++) {
        #pragma unroll
        for (int ks = 0; ks < 4; ks++) {
            uint32_t af[4], bf[4];
            LDSM_X4(af, sb + SMP + pan * 8192 + aP_rb + (((uint32_t)ks * 32 + aP_ks) ^ xorp));
            LDSM_X4_T(bf, sb + SMV + (pan * 64 + ks * 16 + v_row) * 128 + v_doff);
            MMA_F16(accO[0], af, bf[0], bf[1]);
            MMA_F16(accO[1], af, bf[2], bf[3]);
        }
    }

    {
        const int orow = wmp + (lane >> 2);
        const int oc0  = wnp + 2 * (lane & 3);
        #pragma unroll
        for (int nt = 0; nt < 2; nt++) {
            const int c = oc0 + nt * 8;
            *(__half2*)(o + rowBase + (size_t)(start + orow) * C + c) =
                __floats2half2_rn(accO[nt][0], accO[nt][1]);
            *(__half2*)(o + rowBase + (size_t)(start + orow + 8) * C + c) =
                __floats2half2_rn(accO[nt][2], accO[nt][3]);
        }
    }
}

// ---------------------------------------------------------------------------
extern "C" void kernel_launch(void* const* d_in, const int* in_sizes, int n_in,
                              void* d_out, int out_size)
{
    const float* query = (const float*)d_in[0];
    const float* key   = (const float*)d_in[1];
    const float* value = (const float*)d_in[2];
    const float* Wq    = (const float*)d_in[3];
    const float* bq    = (const float*)d_in[4];
    const float* Wk    = (const float*)d_in[5];
    const float* bk    = (const float*)d_in[6];
    const float* Wv    = (const float*)d_in[7];
    const float* bv    = (const float*)d_in[8];
    const float* Wo    = (const float*)d_in[9];
    const float* bo    = (const float*)d_in[10];
    float* out = (float*)d_out;

    __half *gq, *gk, *gv, *ga, *gx, *gw;
    cudaGetSymbolAddress((void**)&gq, g_q);
    cudaGetSymbolAddress((void**)&gk, g_k);
    cudaGetSymbolAddress((void**)&gv, g_v);
    cudaGetSymbolAddress((void**)&ga, g_a);
    cudaGetSymbolAddress((void**)&gx, g_x16);
    cudaGetSymbolAddress((void**)&gw, g_w16);
    const __half* x0 = gx;
    const __half* x1 = gx + (size_t)M * C;
    const __half* x2 = gx + (size_t)2 * M * C;
    const __half* w0 = gw;
    const __half* w1 = gw + (size_t)C * C;
    const __half* w2 = gw + (size_t)2 * C * C;
    const __half* w3 = gw + (size_t)3 * C * C;

    cudaFuncSetAttribute(gemm_mma<true>,
                         cudaFuncAttributeMaxDynamicSharedMemorySize, SM_GEMM);
    cudaFuncSetAttribute(gemm_mma<false>,
                         cudaFuncAttributeMaxDynamicSharedMemorySize, SM_GEMM);
    cudaFuncSetAttribute(attn_kernel,
                         cudaFuncAttributeMaxDynamicSharedMemorySize, SMEM_ATTN);

    conv_all<<<(int)(CONV_TOTAL / 256), 256>>>(
        (const float4*)query, (const float4*)key, (const float4*)value,
        (const float4*)Wq, (const float4*)Wk, (const float4*)Wv, (const float4*)Wo);

    const float scale = 0.125f;   // 64^-0.5

    GemmArgs qkv;
    qkv.A[0] = x0; qkv.A[1] = x1; qkv.A[2] = x2;
    qkv.W[0] = w0; qkv.W[1] = w1; qkv.W[2] = w2;
    qkv.bias[0] = bq; qkv.bias[1] = bk; qkv.bias[2] = bv;
    qkv.Y[0] = gq; qkv.Y[1] = gk; qkv.Y[2] = gv;
    qkv.alpha[0] = scale; qkv.alpha[1] = 1.0f; qkv.alpha[2] = 1.0f;
    gemm_mma<true><<<dim3(C / GBN, M / GBM, 3), 256, SM_GEMM>>>(qkv);

    attn_kernel<<<dim3(NB, H, B), ATHR, SMEM_ATTN>>>(gq, gk, gv, ga);

    GemmArgs og;
    og.A[0] = ga; og.A[1] = ga; og.A[2] = ga;
    og.W[0] = w3; og.W[1] = w3; og.W[2] = w3;
    og.bias[0] = bo; og.bias[1] = bo; og.bias[2] = bo;
    og.Y[0] = out; og.Y[1] = out; og.Y[2] = out;
    og.alpha[0] = 1.0f; og.alpha[1] = 1.0f; og.alpha[2] = 1.0f;
    gemm_mma<false><<<dim3(C / GBN, M / GBM, 1), 256, SM_GEMM>>>(og);
}

// round 13
// speedup vs baseline: 1.0241x; 1.0241x over previous
#include <cuda_runtime.h>
#include <cuda_fp16.h>
#include <math.h>
#include <cstdint>

// ---------------------------------------------------------------------------
// Problem constants
// ---------------------------------------------------------------------------
constexpr int B  = 2;
constexpr int T  = 8192;
constexpr int C  = 1024;
constexpr int H  = 16;
constexpr int BS = 64;
constexpr int LW = 128;
constexpr int D  = 64;
constexpr int WN = BS + LW;     // 192
constexpr int NB = T / BS;      // 128
constexpr int M  = B * T;       // 16384

// ---------------------------------------------------------------------------
// GEMM config: mma.sync m16n8k16 fp16, CTA tile 64x128x64, 4 warps (32x64),
// 3-stage cp.async pipeline, 3 CTAs/SM (reg cap 170 -> ptxas can pipeline
// fragment loads across k-steps; 3 CTAs desync barrier phases).
// ---------------------------------------------------------------------------
constexpr int GBM = 64;
constexpr int GBN = 128;
constexpr int GBK = 64;                       // 64 fp16 = 128B rows
constexpr int NKT = C / GBK;                  // 16
constexpr int GTHR = 128;                     // 4 warps
constexpr int AST = GBM * GBK * 2;            // 8192 B
constexpr int BST = GBN * GBK * 2;            // 16384 B
constexpr int SM_B_OFF = 3 * AST;             // 24576
constexpr int SM_BIAS  = 3 * AST + 3 * BST;   // 73728
constexpr int SM_GEMM  = SM_BIAS + GBN * 4;   // 74240 (x3 CTAs = 222720)

// ---------------------------------------------------------------------------
// Attention smem layout (bytes), fp16 tiles, 128B rows.
// P panels (24KB) OVERLAY the dead Q+K region (32KB) after QK completes.
// ---------------------------------------------------------------------------
constexpr int SMQ   = 0;        // 64 x 128B  = 8KB
constexpr int SMK   = 8192;     // 192 x 128B = 24KB
constexpr int SMV   = 32768;    // 192 x 128B = 24KB
constexpr int SMP   = 0;        // 3 panels x 64 x 128B = 24KB (overlays Q+K)
constexpr int SMRA  = 57344;    // 64 x 4 f32 (max reduce)
constexpr int SMRB  = 58368;    // 64 x 4 f32 (sum reduce)
constexpr int SMEM_ATTN = 59392;
constexpr int ATHR = 512;

// ---------------------------------------------------------------------------
// Scratch
// ---------------------------------------------------------------------------
__device__ __align__(16) __half g_x16[3][(size_t)M * C];   // fp16 inputs
__device__ __align__(16) __half g_w16[4][(size_t)C * C];   // fp16 weights
__device__ __align__(16) __half g_q[(size_t)M * C];
__device__ __align__(16) __half g_k[(size_t)M * C];
__device__ __align__(16) __half g_v[(size_t)M * C];
__device__ __align__(16) __half g_a[(size_t)M * C];

struct GemmArgs {
    const __half* A[3];
    const __half* W[3];
    const float*  bias[3];
    void*         Y[3];
    float         alpha[3];
};

// ---------------------------------------------------------------------------
// PTX helpers (base sm_103-safe)
// ---------------------------------------------------------------------------
__device__ __forceinline__ uint32_t smem_u32(const void* p) {
    uint32_t a;
    asm("{ .reg .u64 t; cvta.to.shared.u64 t, %1; cvt.u32.u64 %0, t; }" : "=r"(a) : "l"(p));
    return a;
}

#define CP_ASYNC16(dst, src) \
    asm volatile("cp.async.cg.shared.global [%0], [%1], 16;" :: "r"(dst), "l"(src) : "memory")
#define CP_COMMIT() asm volatile("cp.async.commit_group;" ::: "memory")
#define CP_WAIT(n)  asm volatile("cp.async.wait_group %0;" :: "n"(n) : "memory")

#define LDSM_X4(r, addr) \
    asm volatile("ldmatrix.sync.aligned.m8n8.x4.shared.b16 {%0,%1,%2,%3}, [%4];" \
        : "=r"((r)[0]), "=r"((r)[1]), "=r"((r)[2]), "=r"((r)[3]) : "r"(addr))

#define LDSM_X4_T(r, addr) \
    asm volatile("ldmatrix.sync.aligned.m8n8.x4.trans.shared.b16 {%0,%1,%2,%3}, [%4];" \
        : "=r"((r)[0]), "=r"((r)[1]), "=r"((r)[2]), "=r"((r)[3]) : "r"(addr))

#define MMA_F16(d, a, b0, b1) \
    asm volatile("mma.sync.aligned.m16n8k16.row.col.f32.f16.f16.f32 " \
        "{%0,%1,%2,%3}, {%4,%5,%6,%7}, {%8,%9}, {%0,%1,%2,%3};" \
        : "+f"((d)[0]), "+f"((d)[1]), "+f"((d)[2]), "+f"((d)[3]) \
        : "r"((a)[0]), "r"((a)[1]), "r"((a)[2]), "r"((a)[3]), "r"(b0), "r"(b1))

// ---------------------------------------------------------------------------
// Prepass: all fp32 -> fp16 conversions in ONE launch.
// ---------------------------------------------------------------------------
constexpr size_t PER4A = (size_t)M * C / 4;   // 4194304 float4 per activation
constexpr size_t PER4W = (size_t)C * C / 4;   // 262144 float4 per weight
constexpr size_t CONV_TOTAL = 3 * PER4A + 4 * PER4W;

__global__ __launch_bounds__(256)
void conv_all(const float4* __restrict__ q, const float4* __restrict__ k,
              const float4* __restrict__ v,
              const float4* __restrict__ w0, const float4* __restrict__ w1,
              const float4* __restrict__ w2, const float4* __restrict__ w3)
{
    size_t i = (size_t)blockIdx.x * 256 + threadIdx.x;
    const float4* src;
    __half2* dst;
    if (i < 3 * PER4A) {
        const int which = (int)(i / PER4A);
        const size_t off = i - (size_t)which * PER4A;
        src = (which == 0 ? q : which == 1 ? k : v) + off;
        dst = (__half2*)&g_x16[which][off * 4];
    } else {
        i -= 3 * PER4A;
        const int which = (int)(i / PER4W);
        const size_t off = i - (size_t)which * PER4W;
        src = (which == 0 ? w0 : which == 1 ? w1 : which == 2 ? w2 : w3) + off;
        dst = (__half2*)&g_w16[which][off * 4];
    }
    float4 x = *src;
    dst[0] = __floats2half2_rn(x.x, x.y);
    dst[1] = __floats2half2_rn(x.z, x.w);
}

// ---------------------------------------------------------------------------
// fp16 GEMM: Y[m,n] = alpha * (sum_k A[m,k] * W[n,k] + bias[n])
// 64x128 CTA tile, 4 warps (2x2 grid of 32x64 warp tiles), 3 CTAs/SM.
// ---------------------------------------------------------------------------
template <bool HALF_OUT>
__global__ __launch_bounds__(GTHR, 3)
void gemm_mma(const GemmArgs args)
{
    extern __shared__ char smem[];
    const uint32_t sA = smem_u32(smem);
    const uint32_t sB = sA + SM_B_OFF;
    float* bsm = (float*)(smem + SM_BIAS);

    const int z = blockIdx.z;
    const __half* A    = args.A[z];
    const __half* Wt   = args.W[z];
    const float*  bias = args.bias[z];
    void*         Y    = args.Y[z];
    const float alpha  = args.alpha[z];

    const int tid  = threadIdx.x;
    const int wid  = tid >> 5;
    const int lane = tid & 31;
    const int bm   = blockIdx.y * GBM;
    const int n0   = blockIdx.x * GBN;

    if (tid < GBN / 4)
        *(float4*)(bsm + tid * 4) = *(const float4*)(bias + n0 + tid * 4);

    auto loadA = [&](int slot, int kt) {
        const __half* src = A + (size_t)bm * C + kt * GBK;
        const uint32_t base = sA + slot * AST;
        #pragma unroll
        for (int c = 0; c < 4; c++) {            // 64 rows x 8 granules = 512
            const int ci = tid + c * GTHR;
            const int r = ci >> 3, g = ci & 7;
            CP_ASYNC16(base + r * 128 + ((g * 16) ^ ((r & 7) * 16)),
                       src + (size_t)r * C + g * 8);
        }
    };
    auto loadB = [&](int slot, int kt) {
        const __half* src = Wt + (size_t)n0 * C + kt * GBK;
        const uint32_t base = sB + slot * BST;
        #pragma unroll
        for (int c = 0; c < 8; c++) {            // 128 rows x 8 granules = 1024
            const int ci = tid + c * GTHR;
            const int r = ci >> 3, g = ci & 7;
            CP_ASYNC16(base + r * 128 + ((g * 16) ^ ((r & 7) * 16)),
                       src + (size_t)r * C + g * 8);
        }
    };

    loadA(0, 0); loadB(0, 0); CP_COMMIT();
    loadA(1, 1); loadB(1, 1); CP_COMMIT();

    float acc[2][8][4];
    #pragma unroll
    for (int i = 0; i < 2; i++)
        #pragma unroll
        for (int j = 0; j < 8; j++)
            #pragma unroll
            for (int l = 0; l < 4; l++) acc[i][j][l] = 0.f;

    const int r8 = lane & 7;
    const int qa = lane >> 3;
    const int wm = (wid & 1) * 32;     // warp m offset (2x2 warp grid)
    const int wn = (wid >> 1) * 64;    // warp n offset
    const uint32_t a_rb   = (wm + (qa & 1) * 8 + r8) * 128;
    const uint32_t a_ksel = (uint32_t)(qa >> 1) * 16;
    const uint32_t b_rb   = (wn + (qa >> 1) * 8 + r8) * 128;
    const uint32_t b_ksel = (uint32_t)(qa & 1) * 16;
    const uint32_t xorp   = (uint32_t)r8 * 16;

    #pragma unroll 3
    for (int kt = 0; kt < NKT; kt++) {
        if (kt < NKT - 2) { CP_WAIT(1); } else { CP_WAIT(0); }
        __syncthreads();
        if (kt + 2 < NKT) {
            const int s2 = (kt + 2) % 3;
            loadA(s2, kt + 2); loadB(s2, kt + 2); CP_COMMIT();
        }
        const int slot = kt % 3;
        const uint32_t aBase = sA + slot * AST + a_rb;
        const uint32_t bBase = sB + slot * BST + b_rb;

        #pragma unroll
        for (int ks = 0; ks < 4; ks++) {
            const uint32_t akoff = ((uint32_t)ks * 32 + a_ksel) ^ xorp;
            const uint32_t bkoff = ((uint32_t)ks * 32 + b_ksel) ^ xorp;
            uint32_t af[2][4], bf[4][4];
            #pragma unroll
            for (int mt = 0; mt < 2; mt++)
                LDSM_X4(af[mt], aBase + mt * (16 * 128) + akoff);
            #pragma unroll
            for (int p = 0; p < 4; p++)
                LDSM_X4(bf[p], bBase + p * (16 * 128) + bkoff);
            #pragma unroll
            for (int mt = 0; mt < 2; mt++)
                #pragma unroll
                for (int p = 0; p < 4; p++) {
                    MMA_F16(acc[mt][2 * p + 0], af[mt], bf[p][0], bf[p][1]);
                    MMA_F16(acc[mt][2 * p + 1], af[mt], bf[p][2], bf[p][3]);
                }
        }
    }

    const int erow  = bm + wm + (lane >> 2);
    const int ecol0 = wn + 2 * (lane & 3);
    #pragma unroll
    for (int mt = 0; mt < 2; mt++) {
        #pragma unroll
        for (int nt = 0; nt < 8; nt++) {
            const int col = ecol0 + nt * 8;
            const float b0 = bsm[col], b1 = bsm[col + 1];
            const float x0 = alpha * (acc[mt][nt][0] + b0);
            const float x1 = alpha * (acc[mt][nt][1] + b1);
            const float x2 = alpha * (acc[mt][nt][2] + b0);
            const float x3 = alpha * (acc[mt][nt][3] + b1);
            if (HALF_OUT) {
                __half* Yh = (__half*)Y;
                *(__half2*)(Yh + (size_t)(erow + mt * 16)     * C + n0 + col) = __floats2half2_rn(x0, x1);
                *(__half2*)(Yh + (size_t)(erow + mt * 16 + 8) * C + n0 + col) = __floats2half2_rn(x2, x3);
            } else {
                float* Yf = (float*)Y;
                float2 lo; lo.x = x0; lo.y = x1;
                float2 hi; hi.x = x2; hi.y = x3;
                *(float2*)(Yf + (size_t)(erow + mt * 16)     * C + n0 + col) = lo;
                *(float2*)(Yf + (size_t)(erow + mt * 16 + 8) * C + n0 + col) = hi;
            }
        }
    }
}

// ---------------------------------------------------------------------------
// fp16 tensor-core block-local attention, 512 threads, 2 CTAs/SM.
// (Unchanged from R8 — known-good.)
// ---------------------------------------------------------------------------
__global__ __launch_bounds__(ATHR, 2)
void attn_kernel(const __half* __restrict__ q, const __half* __restrict__ k,
                 const __half* __restrict__ v, __half* __restrict__ o)
{
    extern __shared__ char smem[];
    const uint32_t sb = smem_u32(smem);
    float* redA = (float*)(smem + SMRA);
    float* redB = (float*)(smem + SMRB);

    const int nb  = blockIdx.x;
    const int h   = blockIdx.y;
    const int b   = blockIdx.z;
    const int tid = threadIdx.x;
    const int wid  = tid >> 5;
    const int lane = tid & 31;
    const int start = nb * BS;
    const size_t rowBase = (size_t)b * T * C + (size_t)h * D;

    const __half* qp = q + rowBase;
    const __half* kp = k + rowBase;
    const __half* vp = v + rowBase;

    {
        {   // Q: 64 rows x 8 granules = 512
            const int r = tid >> 3, g = tid & 7;
            CP_ASYNC16(sb + SMQ + r * 128 + ((g * 16) ^ ((r & 7) * 16)),
                       qp + (size_t)(start + r) * C + g * 8);
        }
        #pragma unroll
        for (int i = 0; i < 3; i++) {   // K: 192 x 8 = 1536
            const int idx = tid + i * ATHR;
            const int r = idx >> 3, g = idx & 7;
            int p = start - LW / 2 + r;
            p = p < 0 ? 0 : (p >= T ? T - 1 : p);
            CP_ASYNC16(sb + SMK + r * 128 + ((g * 16) ^ ((r & 7) * 16)),
                       kp + (size_t)p * C + g * 8);
        }
        CP_COMMIT();
        #pragma unroll
        for (int i = 0; i < 3; i++) {   // V: 192 x 8
            const int idx = tid + i * ATHR;
            const int r = idx >> 3, g = idx & 7;
            int p = start - LW / 2 + r;
            p = p < 0 ? 0 : (p >= T ? T - 1 : p);
            CP_ASYNC16(sb + SMV + r * 128 + ((g * 16) ^ ((r & 7) * 16)),
                       vp + (size_t)p * C + g * 8);
        }
        CP_COMMIT();
    }

    const int r8 = lane & 7;
    const int qa = lane >> 3;
    const uint32_t xorp = (uint32_t)r8 * 16;
    const int kg = wid >> 2;                  // k-group (QK) / d-group (PV)

    const int wmq = (wid & 3) * 16;
    const int wnq = kg * 48;
    const uint32_t aQ_rb = (wmq + (qa & 1) * 8 + r8) * 128;
    const uint32_t aQ_ks = (uint32_t)(qa >> 1) * 16;
    const uint32_t bK_rb = (wnq + (qa >> 1) * 8 + r8) * 128;
    const uint32_t bK_ks = (uint32_t)(qa & 1) * 16;

    float accS[6][4];
    #pragma unroll
    for (int i = 0; i < 6; i++)
        #pragma unroll
        for (int l = 0; l < 4; l++) accS[i][l] = 0.f;

    CP_WAIT(1);
    __syncthreads();

    #pragma unroll
    for (int ks = 0; ks < 4; ks++) {
        uint32_t af[4], bf[3][4];
        LDSM_X4(af, sb + SMQ + aQ_rb + (((uint32_t)ks * 32 + aQ_ks) ^ xorp));
        #pragma unroll
        for (int p = 0; p < 3; p++)
            LDSM_X4(bf[p], sb + SMK + bK_rb + p * (16 * 128) + (((uint32_t)ks * 32 + bK_ks) ^ xorp));
        #pragma unroll
        for (int p = 0; p < 3; p++) {
            MMA_F16(accS[2 * p + 0], af, bf[p][0], bf[p][1]);
            MMA_F16(accS[2 * p + 1], af, bf[p][2], bf[p][3]);
        }
    }

    const int r0 = wmq + (lane >> 2);
    const int r1 = r0 + 8;
    const int c0 = wnq + 2 * (lane & 3);

    float mx0 = -INFINITY, mx1 = -INFINITY;
    #pragma unroll
    for (int nt = 0; nt < 6; nt++) {
        const int ca = c0 + nt * 8, cb = ca + 1;
        const int pa = start - LW / 2 + ca, pb = pa + 1;
        const bool va = (pa >= 0) & (pa < T);
        const bool vb = (pb >= 0) & (pb < T);
        if (!va) { accS[nt][0] = -INFINITY; accS[nt][2] = -INFINITY; }
        if (!vb) { accS[nt][1] = -INFINITY; accS[nt][3] = -INFINITY; }
        mx0 = fmaxf(mx0, fmaxf(accS[nt][0], accS[nt][1]));
        mx1 = fmaxf(mx1, fmaxf(accS[nt][2], accS[nt][3]));
    }
    #pragma unroll
    for (int off = 1; off <= 2; off <<= 1) {
        mx0 = fmaxf(mx0, __shfl_xor_sync(0xffffffffu, mx0, off));
        mx1 = fmaxf(mx1, __shfl_xor_sync(0xffffffffu, mx1, off));
    }
    if ((lane & 3) == 0) { redA[r0 * 4 + kg] = mx0; redA[r1 * 4 + kg] = mx1; }
    __syncthreads();
    mx0 = fmaxf(fmaxf(redA[r0 * 4 + 0], redA[r0 * 4 + 1]),
                fmaxf(redA[r0 * 4 + 2], redA[r0 * 4 + 3]));
    mx1 = fmaxf(fmaxf(redA[r1 * 4 + 0], redA[r1 * 4 + 1]),
                fmaxf(redA[r1 * 4 + 2], redA[r1 * 4 + 3]));

    float s0 = 0.f, s1 = 0.f;
    #pragma unroll
    for (int nt = 0; nt < 6; nt++) {
        accS[nt][0] = __expf(accS[nt][0] - mx0);
        accS[nt][1] = __expf(accS[nt][1] - mx0);
        accS[nt][2] = __expf(accS[nt][2] - mx1);
        accS[nt][3] = __expf(accS[nt][3] - mx1);
        s0 += accS[nt][0] + accS[nt][1];
        s1 += accS[nt][2] + accS[nt][3];
    }
    #pragma unroll
    for (int off = 1; off <= 2; off <<= 1) {
        s0 += __shfl_xor_sync(0xffffffffu, s0, off);
        s1 += __shfl_xor_sync(0xffffffffu, s1, off);
    }
    if ((lane & 3) == 0) { redB[r0 * 4 + kg] = s0; redB[r1 * 4 + kg] = s1; }
    CP_WAIT(0);
    __syncthreads();
    const float inv0 = 1.f / (redB[r0 * 4 + 0] + redB[r0 * 4 + 1] +
                              redB[r0 * 4 + 2] + redB[r0 * 4 + 3]);
    const float inv1 = 1.f / (redB[r1 * 4 + 0] + redB[r1 * 4 + 1] +
                              redB[r1 * 4 + 2] + redB[r1 * 4 + 3]);

    #pragma unroll
    for (int nt = 0; nt < 6; nt++) {
        const int c = c0 + nt * 8;
        const int pan = c >> 6, cc = (c & 63) * 2;
        const uint32_t o0 = SMP + pan * 8192 + r0 * 128 + (cc ^ ((r0 & 7) * 16));
        const uint32_t o1 = SMP + pan * 8192 + r1 * 128 + (cc ^ ((r1 & 7) * 16));
        *(__half2*)(smem + o0) = __floats2half2_rn(accS[nt][0] * inv0, accS[nt][1] * inv0);
        *(__half2*)(smem + o1) = __floats2half2_rn(accS[nt][2] * inv1, accS[nt][3] * inv1);
    }
    __syncthreads();

    const int wmp = (wid & 3) * 16;
    const int wnp = kg * 16;
    const uint32_t aP_rb = (wmp + (qa & 1) * 8 + r8) * 128;
    const uint32_t aP_ks = (uint32_t)(qa >> 1) * 16;
    const uint32_t v_row = (qa & 1) * 8 + r8;
    const uint32_t v_doff = ((uint32_t)wnp * 2 + (uint32_t)(qa >> 1) * 16) ^ xorp;

    float accO[2][4];
    #pragma unroll
    for (int i = 0; i < 2; i++)
        #pragma unroll
        for (int l = 0; l < 4; l++) accO[i][l] = 0.f;

    #pragma unroll
    for (int pan = 0; pan < 3; pan++) {
        #pragma unroll
        for (int ks = 0; ks < 4; ks++) {
            uint32_t af[4], bf[4];
            LDSM_X4(af, sb + SMP + pan * 8192 + aP_rb + (((uint32_t)ks * 32 + aP_ks) ^ xorp));
            LDSM_X4_T(bf, sb + SMV + (pan * 64 + ks * 16 + v_row) * 128 + v_doff);
            MMA_F16(accO[0], af, bf[0], bf[1]);
            MMA_F16(accO[1], af, bf[2], bf[3]);
        }
    }

    {
        const int orow = wmp + (lane >> 2);
        const int oc0  = wnp + 2 * (lane & 3);
        #pragma unroll
        for (int nt = 0; nt < 2; nt++) {
            const int c = oc0 + nt * 8;
            *(__half2*)(o + rowBase + (size_t)(start + orow) * C + c) =
                __floats2half2_rn(accO[nt][0], accO[nt][1]);
            *(__half2*)(o + rowBase + (size_t)(start + orow + 8) * C + c) =
                __floats2half2_rn(accO[nt][2], accO[nt][3]);
        }
    }
}

// ---------------------------------------------------------------------------
extern "C" void kernel_launch(void* const* d_in, const int* in_sizes, int n_in,
                              void* d_out, int out_size)
{
    const float* query = (const float*)d_in[0];
    const float* key   = (const float*)d_in[1];
    const float* value = (const float*)d_in[2];
    const float* Wq    = (const float*)d_in[3];
    const float* bq    = (const float*)d_in[4];
    const float* Wk    = (const float*)d_in[5];
    const float* bk    = (const float*)d_in[6];
    const float* Wv    = (const float*)d_in[7];
    const float* bv    = (const float*)d_in[8];
    const float* Wo    = (const float*)d_in[9];
    const float* bo    = (const float*)d_in[10];
    float* out = (float*)d_out;

    __half *gq, *gk, *gv, *ga, *gx, *gw;
    cudaGetSymbolAddress((void**)&gq, g_q);
    cudaGetSymbolAddress((void**)&gk, g_k);
    cudaGetSymbolAddress((void**)&gv, g_v);
    cudaGetSymbolAddress((void**)&ga, g_a);
    cudaGetSymbolAddress((void**)&gx, g_x16);
    cudaGetSymbolAddress((void**)&gw, g_w16);
    const __half* x0 = gx;
    const __half* x1 = gx + (size_t)M * C;
    const __half* x2 = gx + (size_t)2 * M * C;
    const __half* w0 = gw;
    const __half* w1 = gw + (size_t)C * C;
    const __half* w2 = gw + (size_t)2 * C * C;
    const __half* w3 = gw + (size_t)3 * C * C;

    cudaFuncSetAttribute(gemm_mma<true>,
                         cudaFuncAttributeMaxDynamicSharedMemorySize, SM_GEMM);
    cudaFuncSetAttribute(gemm_mma<false>,
                         cudaFuncAttributeMaxDynamicSharedMemorySize, SM_GEMM);
    cudaFuncSetAttribute(attn_kernel,
                         cudaFuncAttributeMaxDynamicSharedMemorySize, SMEM_ATTN);

    conv_all<<<(int)(CONV_TOTAL / 256), 256>>>(
        (const float4*)query, (const float4*)key, (const float4*)value,
        (const float4*)Wq, (const float4*)Wk, (const float4*)Wv, (const float4*)Wo);

    const float scale = 0.125f;   // 64^-0.5

    GemmArgs qkv;
    qkv.A[0] = x0; qkv.A[1] = x1; qkv.A[2] = x2;
    qkv.W[0] = w0; qkv.W[1] = w1; qkv.W[2] = w2;
    qkv.bias[0] = bq; qkv.bias[1] = bk; qkv.bias[2] = bv;
    qkv.Y[0] = gq; qkv.Y[1] = gk; qkv.Y[2] = gv;
    qkv.alpha[0] = scale; qkv.alpha[1] = 1.0f; qkv.alpha[2] = 1.0f;
    gemm_mma<true><<<dim3(C / GBN, M / GBM, 3), GTHR, SM_GEMM>>>(qkv);

    attn_kernel<<<dim3(NB, H, B), ATHR, SMEM_ATTN>>>(gq, gk, gv, ga);

    GemmArgs og;
    og.A[0] = ga; og.A[1] = ga; og.A[2] = ga;
    og.W[0] = w3; og.W[1] = w3; og.W[2] = w3;
    og.bias[0] = bo; og.bias[1] = bo; og.bias[2] = bo;
    og.Y[0] = out; og.Y[1] = out; og.Y[2] = out;
    og.alpha[0] = 1.0f; og.alpha[1] = 1.0f; og.alpha[2] = 1.0f;
    gemm_mma<false><<<dim3(C / GBN, M / GBM, 1), GTHR, SM_GEMM>>>(og);
}

// round 14
// speedup vs baseline: 1.0350x; 1.0106x over previous
#include <cuda_runtime.h>
#include <cuda_fp16.h>
#include <math.h>
#include <cstdint>

// ---------------------------------------------------------------------------
// Problem constants
// ---------------------------------------------------------------------------
constexpr int B  = 2;
constexpr int T  = 8192;
constexpr int C  = 1024;
constexpr int H  = 16;
constexpr int BS = 64;
constexpr int LW = 128;
constexpr int D  = 64;
constexpr int WN = BS + LW;     // 192
constexpr int NB = T / BS;      // 128
constexpr int M  = B * T;       // 16384

// ---------------------------------------------------------------------------
// GEMM config (R13, known-good): m16n8k16 fp16, CTA tile 64x128x64, 4 warps,
// 3-stage cp.async pipeline, 3 CTAs/SM.
// ---------------------------------------------------------------------------
constexpr int GBM = 64;
constexpr int GBN = 128;
constexpr int GBK = 64;                       // 64 fp16 = 128B rows
constexpr int NKT = C / GBK;                  // 16
constexpr int GTHR = 128;                     // 4 warps
constexpr int AST = GBM * GBK * 2;            // 8192 B
constexpr int BST = GBN * GBK * 2;            // 16384 B
constexpr int SM_B_OFF = 3 * AST;             // 24576
constexpr int SM_BIAS  = 3 * AST + 3 * BST;   // 73728
constexpr int SM_GEMM  = SM_BIAS + GBN * 4;   // 74240 (x3 CTAs = 222720)

// ---------------------------------------------------------------------------
// Attention (2 q-blocks per CTA) smem layout, fp16 tiles, 128B rows.
//   Q: 128 rows (16KB), K: 256 rows (32KB), V: 256 rows (32KB),
//   P: 3 panels x 64 x 128B (24KB, own region), reduce bufs 2KB.
// ---------------------------------------------------------------------------
constexpr int SMQ   = 0;        // 16384
constexpr int SMK   = 16384;    // +32768 = 49152
constexpr int SMV   = 49152;    // +32768 = 81920
constexpr int SMP   = 81920;    // +24576 = 106496
constexpr int SMRA  = 106496;   // 64 x 4 f32
constexpr int SMRB  = 107520;   // 64 x 4 f32
constexpr int SMEM_ATTN = 108544;   // x2 CTAs = 217088 <= 228KB
constexpr int ATHR = 512;

// ---------------------------------------------------------------------------
// Scratch
// ---------------------------------------------------------------------------
__device__ __align__(16) __half g_x16[3][(size_t)M * C];   // fp16 inputs
__device__ __align__(16) __half g_w16[4][(size_t)C * C];   // fp16 weights
__device__ __align__(16) __half g_q[(size_t)M * C];
__device__ __align__(16) __half g_k[(size_t)M * C];
__device__ __align__(16) __half g_v[(size_t)M * C];
__device__ __align__(16) __half g_a[(size_t)M * C];

struct GemmArgs {
    const __half* A[3];
    const __half* W[3];
    const float*  bias[3];
    void*         Y[3];
    float         alpha[3];
};

// ---------------------------------------------------------------------------
// PTX helpers (base sm_103-safe)
// ---------------------------------------------------------------------------
__device__ __forceinline__ uint32_t smem_u32(const void* p) {
    uint32_t a;
    asm("{ .reg .u64 t; cvta.to.shared.u64 t, %1; cvt.u32.u64 %0, t; }" : "=r"(a) : "l"(p));
    return a;
}

#define CP_ASYNC16(dst, src) \
    asm volatile("cp.async.cg.shared.global [%0], [%1], 16;" :: "r"(dst), "l"(src) : "memory")
#define CP_COMMIT() asm volatile("cp.async.commit_group;" ::: "memory")
#define CP_WAIT(n)  asm volatile("cp.async.wait_group %0;" :: "n"(n) : "memory")

#define LDSM_X4(r, addr) \
    asm volatile("ldmatrix.sync.aligned.m8n8.x4.shared.b16 {%0,%1,%2,%3}, [%4];" \
        : "=r"((r)[0]), "=r"((r)[1]), "=r"((r)[2]), "=r"((r)[3]) : "r"(addr))

#define LDSM_X4_T(r, addr) \
    asm volatile("ldmatrix.sync.aligned.m8n8.x4.trans.shared.b16 {%0,%1,%2,%3}, [%4];" \
        : "=r"((r)[0]), "=r"((r)[1]), "=r"((r)[2]), "=r"((r)[3]) : "r"(addr))

#define MMA_F16(d, a, b0, b1) \
    asm volatile("mma.sync.aligned.m16n8k16.row.col.f32.f16.f16.f32 " \
        "{%0,%1,%2,%3}, {%4,%5,%6,%7}, {%8,%9}, {%0,%1,%2,%3};" \
        : "+f"((d)[0]), "+f"((d)[1]), "+f"((d)[2]), "+f"((d)[3]) \
        : "r"((a)[0]), "r"((a)[1]), "r"((a)[2]), "r"((a)[3]), "r"(b0), "r"(b1))

// ---------------------------------------------------------------------------
// Prepass: all fp32 -> fp16 conversions in ONE launch.
// ---------------------------------------------------------------------------
constexpr size_t PER4A = (size_t)M * C / 4;
constexpr size_t PER4W = (size_t)C * C / 4;
constexpr size_t CONV_TOTAL = 3 * PER4A + 4 * PER4W;

__global__ __launch_bounds__(256)
void conv_all(const float4* __restrict__ q, const float4* __restrict__ k,
              const float4* __restrict__ v,
              const float4* __restrict__ w0, const float4* __restrict__ w1,
              const float4* __restrict__ w2, const float4* __restrict__ w3)
{
    size_t i = (size_t)blockIdx.x * 256 + threadIdx.x;
    const float4* src;
    __half2* dst;
    if (i < 3 * PER4A) {
        const int which = (int)(i / PER4A);
        const size_t off = i - (size_t)which * PER4A;
        src = (which == 0 ? q : which == 1 ? k : v) + off;
        dst = (__half2*)&g_x16[which][off * 4];
    } else {
        i -= 3 * PER4A;
        const int which = (int)(i / PER4W);
        const size_t off = i - (size_t)which * PER4W;
        src = (which == 0 ? w0 : which == 1 ? w1 : which == 2 ? w2 : w3) + off;
        dst = (__half2*)&g_w16[which][off * 4];
    }
    float4 x = *src;
    dst[0] = __floats2half2_rn(x.x, x.y);
    dst[1] = __floats2half2_rn(x.z, x.w);
}

// ---------------------------------------------------------------------------
// fp16 GEMM (R13, unchanged): Y = alpha * (A @ W^T + bias)
// ---------------------------------------------------------------------------
template <bool HALF_OUT>
__global__ __launch_bounds__(GTHR, 3)
void gemm_mma(const GemmArgs args)
{
    extern __shared__ char smem[];
    const uint32_t sA = smem_u32(smem);
    const uint32_t sB = sA + SM_B_OFF;
    float* bsm = (float*)(smem + SM_BIAS);

    const int z = blockIdx.z;
    const __half* A    = args.A[z];
    const __half* Wt   = args.W[z];
    const float*  bias = args.bias[z];
    void*         Y    = args.Y[z];
    const float alpha  = args.alpha[z];

    const int tid  = threadIdx.x;
    const int wid  = tid >> 5;
    const int lane = tid & 31;
    const int bm   = blockIdx.y * GBM;
    const int n0   = blockIdx.x * GBN;

    if (tid < GBN / 4)
        *(float4*)(bsm + tid * 4) = *(const float4*)(bias + n0 + tid * 4);

    auto loadA = [&](int slot, int kt) {
        const __half* src = A + (size_t)bm * C + kt * GBK;
        const uint32_t base = sA + slot * AST;
        #pragma unroll
        for (int c = 0; c < 4; c++) {
            const int ci = tid + c * GTHR;
            const int r = ci >> 3, g = ci & 7;
            CP_ASYNC16(base + r * 128 + ((g * 16) ^ ((r & 7) * 16)),
                       src + (size_t)r * C + g * 8);
        }
    };
    auto loadB = [&](int slot, int kt) {
        const __half* src = Wt + (size_t)n0 * C + kt * GBK;
        const uint32_t base = sB + slot * BST;
        #pragma unroll
        for (int c = 0; c < 8; c++) {
            const int ci = tid + c * GTHR;
            const int r = ci >> 3, g = ci & 7;
            CP_ASYNC16(base + r * 128 + ((g * 16) ^ ((r & 7) * 16)),
                       src + (size_t)r * C + g * 8);
        }
    };

    loadA(0, 0); loadB(0, 0); CP_COMMIT();
    loadA(1, 1); loadB(1, 1); CP_COMMIT();

    float acc[2][8][4];
    #pragma unroll
    for (int i = 0; i < 2; i++)
        #pragma unroll
        for (int j = 0; j < 8; j++)
            #pragma unroll
            for (int l = 0; l < 4; l++) acc[i][j][l] = 0.f;

    const int r8 = lane & 7;
    const int qa = lane >> 3;
    const int wm = (wid & 1) * 32;
    const int wn = (wid >> 1) * 64;
    const uint32_t a_rb   = (wm + (qa & 1) * 8 + r8) * 128;
    const uint32_t a_ksel = (uint32_t)(qa >> 1) * 16;
    const uint32_t b_rb   = (wn + (qa >> 1) * 8 + r8) * 128;
    const uint32_t b_ksel = (uint32_t)(qa & 1) * 16;
    const uint32_t xorp   = (uint32_t)r8 * 16;

    #pragma unroll 3
    for (int kt = 0; kt < NKT; kt++) {
        if (kt < NKT - 2) { CP_WAIT(1); } else { CP_WAIT(0); }
        __syncthreads();
        if (kt + 2 < NKT) {
            const int s2 = (kt + 2) % 3;
            loadA(s2, kt + 2); loadB(s2, kt + 2); CP_COMMIT();
        }
        const int slot = kt % 3;
        const uint32_t aBase = sA + slot * AST + a_rb;
        const uint32_t bBase = sB + slot * BST + b_rb;

        #pragma unroll
        for (int ks = 0; ks < 4; ks++) {
            const uint32_t akoff = ((uint32_t)ks * 32 + a_ksel) ^ xorp;
            const uint32_t bkoff = ((uint32_t)ks * 32 + b_ksel) ^ xorp;
            uint32_t af[2][4], bf[4][4];
            #pragma unroll
            for (int mt = 0; mt < 2; mt++)
                LDSM_X4(af[mt], aBase + mt * (16 * 128) + akoff);
            #pragma unroll
            for (int p = 0; p < 4; p++)
                LDSM_X4(bf[p], bBase + p * (16 * 128) + bkoff);
            #pragma unroll
            for (int mt = 0; mt < 2; mt++)
                #pragma unroll
                for (int p = 0; p < 4; p++) {
                    MMA_F16(acc[mt][2 * p + 0], af[mt], bf[p][0], bf[p][1]);
                    MMA_F16(acc[mt][2 * p + 1], af[mt], bf[p][2], bf[p][3]);
                }
        }
    }

    const int erow  = bm + wm + (lane >> 2);
    const int ecol0 = wn + 2 * (lane & 3);
    #pragma unroll
    for (int mt = 0; mt < 2; mt++) {
        #pragma unroll
        for (int nt = 0; nt < 8; nt++) {
            const int col = ecol0 + nt * 8;
            const float b0 = bsm[col], b1 = bsm[col + 1];
            const float x0 = alpha * (acc[mt][nt][0] + b0);
            const float x1 = alpha * (acc[mt][nt][1] + b1);
            const float x2 = alpha * (acc[mt][nt][2] + b0);
            const float x3 = alpha * (acc[mt][nt][3] + b1);
            if (HALF_OUT) {
                __half* Yh = (__half*)Y;
                *(__half2*)(Yh + (size_t)(erow + mt * 16)     * C + n0 + col) = __floats2half2_rn(x0, x1);
                *(__half2*)(Yh + (size_t)(erow + mt * 16 + 8) * C + n0 + col) = __floats2half2_rn(x2, x3);
            } else {
                float* Yf = (float*)Y;
                float2 lo; lo.x = x0; lo.y = x1;
                float2 hi; hi.x = x2; hi.y = x3;
                *(float2*)(Yf + (size_t)(erow + mt * 16)     * C + n0 + col) = lo;
                *(float2*)(Yf + (size_t)(erow + mt * 16 + 8) * C + n0 + col) = hi;
            }
        }
    }
}

// ---------------------------------------------------------------------------
// fp16 tensor-core attention: TWO q-blocks per CTA sharing a 256-row K/V
// union window. Each pass is the R8-proven 64-row pipeline with row-base
// offsets qb*64 (multiple of 8 -> swizzle pattern unchanged).
// ---------------------------------------------------------------------------
__global__ __launch_bounds__(ATHR, 2)
void attn_kernel(const __half* __restrict__ q, const __half* __restrict__ k,
                 const __half* __restrict__ v, __half* __restrict__ o)
{
    extern __shared__ char smem[];
    const uint32_t sb = smem_u32(smem);
    float* redA = (float*)(smem + SMRA);
    float* redB = (float*)(smem + SMRB);

    const int nb2 = blockIdx.x;              // pair index
    const int h   = blockIdx.y;
    const int b   = blockIdx.z;
    const int tid = threadIdx.x;
    const int wid  = tid >> 5;
    const int lane = tid & 31;
    const int start0 = nb2 * (2 * BS);       // first block start
    const int wstart = start0 - LW / 2;      // union window start (256 rows)
    const size_t rowBase = (size_t)b * T * C + (size_t)h * D;

    const __half* qp = q + rowBase;
    const __half* kp = k + rowBase;
    const __half* vp = v + rowBase;

    // --- cp.async: group0 = Q(128) + K(256), group1 = V(256). ---
    {
        #pragma unroll
        for (int i = 0; i < 2; i++) {   // Q: 128 rows x 8 granules
            const int idx = tid + i * ATHR;
            const int r = idx >> 3, g = idx & 7;
            CP_ASYNC16(sb + SMQ + r * 128 + ((g * 16) ^ ((r & 7) * 16)),
                       qp + (size_t)(start0 + r) * C + g * 8);
        }
        #pragma unroll
        for (int i = 0; i < 4; i++) {   // K: 256 rows x 8 granules
            const int idx = tid + i * ATHR;
            const int r = idx >> 3, g = idx & 7;
            int p = wstart + r;
            p = p < 0 ? 0 : (p >= T ? T - 1 : p);
            CP_ASYNC16(sb + SMK + r * 128 + ((g * 16) ^ ((r & 7) * 16)),
                       kp + (size_t)p * C + g * 8);
        }
        CP_COMMIT();
        #pragma unroll
        for (int i = 0; i < 4; i++) {   // V: 256 rows x 8 granules
            const int idx = tid + i * ATHR;
            const int r = idx >> 3, g = idx & 7;
            int p = wstart + r;
            p = p < 0 ? 0 : (p >= T ? T - 1 : p);
            CP_ASYNC16(sb + SMV + r * 128 + ((g * 16) ^ ((r & 7) * 16)),
                       vp + (size_t)p * C + g * 8);
        }
        CP_COMMIT();
    }

    const int r8 = lane & 7;
    const int qa = lane >> 3;
    const uint32_t xorp = (uint32_t)r8 * 16;
    const int kg = wid >> 2;                  // k-group (QK) / d-group (PV)

    const int wmq = (wid & 3) * 16;
    const int wnq = kg * 48;
    const uint32_t aQ_rb = (wmq + (qa & 1) * 8 + r8) * 128;
    const uint32_t aQ_ks = (uint32_t)(qa >> 1) * 16;
    const uint32_t bK_rb = (wnq + (qa >> 1) * 8 + r8) * 128;
    const uint32_t bK_ks = (uint32_t)(qa & 1) * 16;

    const int r0 = wmq + (lane >> 2);
    const int r1 = r0 + 8;
    const int c0 = wnq + 2 * (lane & 3);

    const int wmp = (wid & 3) * 16;
    const int wnp = kg * 16;
    const uint32_t aP_rb = (wmp + (qa & 1) * 8 + r8) * 128;
    const uint32_t aP_ks = (uint32_t)(qa >> 1) * 16;
    const uint32_t v_row = (qa & 1) * 8 + r8;
    const uint32_t v_doff = ((uint32_t)wnp * 2 + (uint32_t)(qa >> 1) * 16) ^ xorp;

    CP_WAIT(1);
    __syncthreads();

    #pragma unroll 1
    for (int qb = 0; qb < 2; qb++) {
        const int start = start0 + qb * BS;        // this block's start
        const uint32_t qoff = (uint32_t)qb * 8192; // 64 rows x 128B
        // K/V slice for this block: union rows [qb*64, qb*64+192)

        // --- QK^T ---
        float accS[6][4];
        #pragma unroll
        for (int i = 0; i < 6; i++)
            #pragma unroll
            for (int l = 0; l < 4; l++) accS[i][l] = 0.f;

        #pragma unroll
        for (int ks = 0; ks < 4; ks++) {
            uint32_t af[4], bf[3][4];
            LDSM_X4(af, sb + SMQ + qoff + aQ_rb + (((uint32_t)ks * 32 + aQ_ks) ^ xorp));
            #pragma unroll
            for (int p = 0; p < 3; p++)
                LDSM_X4(bf[p], sb + SMK + qoff + bK_rb + p * (16 * 128) +
                                (((uint32_t)ks * 32 + bK_ks) ^ xorp));
            #pragma unroll
            for (int p = 0; p < 3; p++) {
                MMA_F16(accS[2 * p + 0], af, bf[p][0], bf[p][1]);
                MMA_F16(accS[2 * p + 1], af, bf[p][2], bf[p][3]);
            }
        }

        // --- masked softmax (register) ---
        float mx0 = -INFINITY, mx1 = -INFINITY;
        #pragma unroll
        for (int nt = 0; nt < 6; nt++) {
            const int ca = c0 + nt * 8;
            const int pa = start - LW / 2 + ca, pb = pa + 1;
            const bool va = (pa >= 0) & (pa < T);
            const bool vb = (pb >= 0) & (pb < T);
            if (!va) { accS[nt][0] = -INFINITY; accS[nt][2] = -INFINITY; }
            if (!vb) { accS[nt][1] = -INFINITY; accS[nt][3] = -INFINITY; }
            mx0 = fmaxf(mx0, fmaxf(accS[nt][0], accS[nt][1]));
            mx1 = fmaxf(mx1, fmaxf(accS[nt][2], accS[nt][3]));
        }
        #pragma unroll
        for (int off = 1; off <= 2; off <<= 1) {
            mx0 = fmaxf(mx0, __shfl_xor_sync(0xffffffffu, mx0, off));
            mx1 = fmaxf(mx1, __shfl_xor_sync(0xffffffffu, mx1, off));
        }
        if ((lane & 3) == 0) { redA[r0 * 4 + kg] = mx0; redA[r1 * 4 + kg] = mx1; }
        __syncthreads();   // also orders prior pass's P reads before P rewrite
        mx0 = fmaxf(fmaxf(redA[r0 * 4 + 0], redA[r0 * 4 + 1]),
                    fmaxf(redA[r0 * 4 + 2], redA[r0 * 4 + 3]));
        mx1 = fmaxf(fmaxf(redA[r1 * 4 + 0], redA[r1 * 4 + 1]),
                    fmaxf(redA[r1 * 4 + 2], redA[r1 * 4 + 3]));

        float s0 = 0.f, s1 = 0.f;
        #pragma unroll
        for (int nt = 0; nt < 6; nt++) {
            accS[nt][0] = __expf(accS[nt][0] - mx0);
            accS[nt][1] = __expf(accS[nt][1] - mx0);
            accS[nt][2] = __expf(accS[nt][2] - mx1);
            accS[nt][3] = __expf(accS[nt][3] - mx1);
            s0 += accS[nt][0] + accS[nt][1];
            s1 += accS[nt][2] + accS[nt][3];
        }
        #pragma unroll
        for (int off = 1; off <= 2; off <<= 1) {
            s0 += __shfl_xor_sync(0xffffffffu, s0, off);
            s1 += __shfl_xor_sync(0xffffffffu, s1, off);
        }
        if ((lane & 3) == 0) { redB[r0 * 4 + kg] = s0; redB[r1 * 4 + kg] = s1; }
        if (qb == 0) { CP_WAIT(0); }     // V resident before first PV
        __syncthreads();
        const float inv0 = 1.f / (redB[r0 * 4 + 0] + redB[r0 * 4 + 1] +
                                  redB[r0 * 4 + 2] + redB[r0 * 4 + 3]);
        const float inv1 = 1.f / (redB[r1 * 4 + 0] + redB[r1 * 4 + 1] +
                                  redB[r1 * 4 + 2] + redB[r1 * 4 + 3]);

        // write P (fp16) into swizzled k64-panels
        #pragma unroll
        for (int nt = 0; nt < 6; nt++) {
            const int c = c0 + nt * 8;
            const int pan = c >> 6, cc = (c & 63) * 2;
            const uint32_t o0 = SMP + pan * 8192 + r0 * 128 + (cc ^ ((r0 & 7) * 16));
            const uint32_t o1 = SMP + pan * 8192 + r1 * 128 + (cc ^ ((r1 & 7) * 16));
            *(__half2*)(smem + o0) = __floats2half2_rn(accS[nt][0] * inv0, accS[nt][1] * inv0);
            *(__half2*)(smem + o1) = __floats2half2_rn(accS[nt][2] * inv1, accS[nt][3] * inv1);
        }
        __syncthreads();

        // --- P @ V ---
        float accO[2][4];
        #pragma unroll
        for (int i = 0; i < 2; i++)
            #pragma unroll
            for (int l = 0; l < 4; l++) accO[i][l] = 0.f;

        #pragma unroll
        for (int pan = 0; pan < 3; pan++) {
            #pragma unroll
            for (int ks = 0; ks < 4; ks++) {
                uint32_t af[4], bf[4];
                LDSM_X4(af, sb + SMP + pan * 8192 + aP_rb +
                            (((uint32_t)ks * 32 + aP_ks) ^ xorp));
                LDSM_X4_T(bf, sb + SMV + qoff +
                              (pan * 64 + ks * 16 + v_row) * 128 + v_doff);
                MMA_F16(accO[0], af, bf[0], bf[1]);
                MMA_F16(accO[1], af, bf[2], bf[3]);
            }
        }

        // write O (fp16)
        {
            const int orow = wmp + (lane >> 2);
            const int oc0  = wnp + 2 * (lane & 3);
            #pragma unroll
            for (int nt = 0; nt < 2; nt++) {
                const int c = oc0 + nt * 8;
                *(__half2*)(o + rowBase + (size_t)(start + orow) * C + c) =
                    __floats2half2_rn(accO[nt][0], accO[nt][1]);
                *(__half2*)(o + rowBase + (size_t)(start + orow + 8) * C + c) =
                    __floats2half2_rn(accO[nt][2], accO[nt][3]);
            }
        }
    }
}

// ---------------------------------------------------------------------------
extern "C" void kernel_launch(void* const* d_in, const int* in_sizes, int n_in,
                              void* d_out, int out_size)
{
    const float* query = (const float*)d_in[0];
    const float* key   = (const float*)d_in[1];
    const float* value = (const float*)d_in[2];
    const float* Wq    = (const float*)d_in[3];
    const float* bq    = (const float*)d_in[4];
    const float* Wk    = (const float*)d_in[5];
    const float* bk    = (const float*)d_in[6];
    const float* Wv    = (const float*)d_in[7];
    const float* bv    = (const float*)d_in[8];
    const float* Wo    = (const float*)d_in[9];
    const float* bo    = (const float*)d_in[10];
    float* out = (float*)d_out;

    __half *gq, *gk, *gv, *ga, *gx, *gw;
    cudaGetSymbolAddress((void**)&gq, g_q);
    cudaGetSymbolAddress((void**)&gk, g_k);
    cudaGetSymbolAddress((void**)&gv, g_v);
    cudaGetSymbolAddress((void**)&ga, g_a);
    cudaGetSymbolAddress((void**)&gx, g_x16);
    cudaGetSymbolAddress((void**)&gw, g_w16);
    const __half* x0 = gx;
    const __half* x1 = gx + (size_t)M * C;
    const __half* x2 = gx + (size_t)2 * M * C;
    const __half* w0 = gw;
    const __half* w1 = gw + (size_t)C * C;
    const __half* w2 = gw + (size_t)2 * C * C;
    const __half* w3 = gw + (size_t)3 * C * C;

    cudaFuncSetAttribute(gemm_mma<true>,
                         cudaFuncAttributeMaxDynamicSharedMemorySize, SM_GEMM);
    cudaFuncSetAttribute(gemm_mma<false>,
                         cudaFuncAttributeMaxDynamicSharedMemorySize, SM_GEMM);
    cudaFuncSetAttribute(attn_kernel,
                         cudaFuncAttributeMaxDynamicSharedMemorySize, SMEM_ATTN);

    conv_all<<<(int)(CONV_TOTAL / 256), 256>>>(
        (const float4*)query, (const float4*)key, (const float4*)value,
        (const float4*)Wq, (const float4*)Wk, (const float4*)Wv, (const float4*)Wo);

    const float scale = 0.125f;   // 64^-0.5

    GemmArgs qkv;
    qkv.A[0] = x0; qkv.A[1] = x1; qkv.A[2] = x2;
    qkv.W[0] = w0; qkv.W[1] = w1; qkv.W[2] = w2;
    qkv.bias[0] = bq; qkv.bias[1] = bk; qkv.bias[2] = bv;
    qkv.Y[0] = gq; qkv.Y[1] = gk; qkv.Y[2] = gv;
    qkv.alpha[0] = scale; qkv.alpha[1] = 1.0f; qkv.alpha[2] = 1.0f;
    gemm_mma<true><<<dim3(C / GBN, M / GBM, 3), GTHR, SM_GEMM>>>(qkv);

    attn_kernel<<<dim3(NB / 2, H, B), ATHR, SMEM_ATTN>>>(gq, gk, gv, ga);

    GemmArgs og;
    og.A[0] = ga; og.A[1] = ga; og.A[2] = ga;
    og.W[0] = w3; og.W[1] = w3; og.W[2] = w3;
    og.bias[0] = bo; og.bias[1] = bo; og.bias[2] = bo;
    og.Y[0] = out; og.Y[1] = out; og.Y[2] = out;
    og.alpha[0] = 1.0f; og.alpha[1] = 1.0f; og.alpha[2] = 1.0f;
    gemm_mma<false><<<dim3(C / GBN, M / GBM, 1), GTHR, SM_GEMM>>>(og);
}